// round 11
// baseline (speedup 1.0000x reference)
#include <cuda_runtime.h>
#include <cuda_fp16.h>
#include <cuda_bf16.h>
#include <cstddef>

#define B_   4
#define D_   256
#define E_   512
#define C_   256
#define NEG_INF -1e9f

typedef unsigned long long ull;

// Scratch. h buffers: proj as half at natural col index (c%8 in {6,7} unused).
// f buffers: tanh(proj) as f32 for c%8 in {6,7}: index = (c>>3)*2 + (c&1).
__device__ __half g_enc_h[B_ * E_ * 256];
__device__ float  g_enc_f[B_ * E_ * 64];
__device__ __half g_dec_h[B_ * D_ * 256];
__device__ float  g_dec_f[B_ * D_ * 64];
__device__ float  g_scores[B_ * D_ * E_];

__device__ __forceinline__ __half2 tanh2h(__half2 x) {
    unsigned int r, xi = *reinterpret_cast<unsigned int*>(&x);
    asm("tanh.approx.f16x2 %0, %1;" : "=r"(r) : "r"(xi));
    return *reinterpret_cast<__half2*>(&r);
}
__device__ __forceinline__ __half2 u2h(unsigned int u) {
    return *reinterpret_cast<__half2*>(&u);
}
__device__ __forceinline__ float tanhf_fast(float x) {
    float y; asm("tanh.approx.f32 %0, %1;" : "=f"(y) : "f"(x)); return y;
}
__device__ __forceinline__ ull fma2_(ull a, ull b, ull c) {
    ull d; asm("fma.rn.f32x2 %0, %1, %2, %3;" : "=l"(d) : "l"(a), "l"(b), "l"(c)); return d;
}
__device__ __forceinline__ ull add2_(ull a, ull b) {
    ull d; asm("add.rn.f32x2 %0, %1, %2;" : "=l"(d) : "l"(a), "l"(b)); return d;
}
__device__ __forceinline__ ull mul2_(ull a, ull b) {
    ull d; asm("mul.rn.f32x2 %0, %1, %2;" : "=l"(d) : "l"(a), "l"(b)); return d;
}

#define ONE2_  0x3F8000003F800000ull
#define NTWO2_ 0xC0000000C0000000ull

// tanh(a+b)*v via addition formula, 1 Newton step.
// ta, tb = packed f32 tanh pairs; nv = packed(-v). 6 f32x2 + 2 ALU.
__device__ __forceinline__ ull tanh_sum_acc1(ull ta, ull tb, ull nv, ull acc) {
    ull num = add2_(ta, tb);
    ull den = fma2_(ta, tb, ONE2_);          // 1 + ta*tb in (0,2]
    ull r0;
    asm("{\n\t.reg .b32 lo, hi;\n\t"
        "mov.b64 {lo, hi}, %1;\n\t"
        "sub.u32 lo, 0x7EF311C3, lo;\n\t"
        "sub.u32 hi, 0x7EF311C3, hi;\n\t"
        "mov.b64 %0, {lo, hi};\n\t}" : "=l"(r0) : "l"(den));
    ull u1  = fma2_(den, r0, NTWO2_);        // d*r0 - 2
    ull r1n = mul2_(r0, u1);                 // -r1 ~ -1/den
    ull t   = mul2_(num, r1n);               // -tanh(a+b)
    return fma2_(t, nv, acc);                // acc + tanh*v
}

// ---------------------------------------------------------------------------
// Fused GEMM v2: tile 32 rows x 32 cols, BK=16, 128 threads, 2x4 micro-tile.
// grid: x = 8 col tiles, y = 24 row tiles (0..15 enc R=512, 16..23 dec R=256),
// z = B. 768 CTAs -> ~5.2 CTA/SM, ~21 warps/SM (vs 10 before).
// Epilogue: tx even -> 4 halves (c%8 0..3); tx odd -> 2 halves (c%8 4,5)
// + 2 tanh'd f32 (c%8 6,7).
// ---------------------------------------------------------------------------
__global__ __launch_bounds__(128) void gemm_fused_kernel(
        const float* __restrict__ enc, const float* __restrict__ dec,
        const float* __restrict__ W1,  const float* __restrict__ W2) {
    __shared__ float Xs[16][36];
    __shared__ float Ws[16][36];

    const int b  = blockIdx.z;
    const int yt = blockIdx.y;
    const bool is_enc = (yt < 16);
    const int R      = is_enc ? E_ : D_;
    const int row0   = (is_enc ? yt : yt - 16) * 32;
    const int col0   = blockIdx.x * 32;
    const float* X   = is_enc ? enc : dec;
    const float* W   = is_enc ? W1  : W2;
    __half* outh     = is_enc ? g_enc_h : g_dec_h;
    float*  outf     = is_enc ? g_enc_f : g_dec_f;

    const int t  = threadIdx.x;
    const int lr = t >> 2;           // 0..31 (row for fills)
    const int lc = (t & 3) << 2;     // 0,4,8,12 (k-offset for fills)
    const int ty = t >> 3;           // 0..15 -> rows {2ty, 2ty+1}
    const int tx = t & 7;            // 0..7  -> cols {4tx .. 4tx+3}

    const float* Xb = X + ((size_t)b * R + row0 + lr) * C_ + lc;
    const float* Wb = W + (size_t)(col0 + lr) * C_ + lc;

    float4 xa = *(const float4*)Xb;
    float4 wa = *(const float4*)Wb;

    float acc[2][4];
#pragma unroll
    for (int i = 0; i < 2; i++)
#pragma unroll
        for (int j = 0; j < 4; j++) acc[i][j] = 0.f;

    for (int k0 = 0; k0 < C_; k0 += 16) {
        Xs[lc + 0][lr] = xa.x; Xs[lc + 1][lr] = xa.y;
        Xs[lc + 2][lr] = xa.z; Xs[lc + 3][lr] = xa.w;
        Ws[lc + 0][lr] = wa.x; Ws[lc + 1][lr] = wa.y;
        Ws[lc + 2][lr] = wa.z; Ws[lc + 3][lr] = wa.w;
        __syncthreads();
        if (k0 + 16 < C_) {
            xa = *(const float4*)(Xb + k0 + 16);
            wa = *(const float4*)(Wb + k0 + 16);
        }
#pragma unroll
        for (int kk = 0; kk < 16; kk++) {
            float2 a2 = *(const float2*)&Xs[kk][2 * ty];
            float4 b4 = *(const float4*)&Ws[kk][4 * tx];
            acc[0][0] = fmaf(a2.x, b4.x, acc[0][0]);
            acc[0][1] = fmaf(a2.x, b4.y, acc[0][1]);
            acc[0][2] = fmaf(a2.x, b4.z, acc[0][2]);
            acc[0][3] = fmaf(a2.x, b4.w, acc[0][3]);
            acc[1][0] = fmaf(a2.y, b4.x, acc[1][0]);
            acc[1][1] = fmaf(a2.y, b4.y, acc[1][1]);
            acc[1][2] = fmaf(a2.y, b4.z, acc[1][2]);
            acc[1][3] = fmaf(a2.y, b4.w, acc[1][3]);
        }
        __syncthreads();
    }

    const int G = (col0 >> 3) + (tx >> 1);   // global c-group of this thread
#pragma unroll
    for (int i = 0; i < 2; i++) {
        const size_t r = (size_t)b * R + row0 + 2 * ty + i;
        if ((tx & 1) == 0) {
            // cols 8G..8G+3 -> h buffer
            __half2 h0 = __floats2half2_rn(acc[i][0], acc[i][1]);
            __half2 h1 = __floats2half2_rn(acc[i][2], acc[i][3]);
            uint2 pk = make_uint2(*reinterpret_cast<unsigned int*>(&h0),
                                  *reinterpret_cast<unsigned int*>(&h1));
            *(uint2*)(outh + r * 256 + 8 * G) = pk;
        } else {
            // cols 8G+4,8G+5 -> h; 8G+6,8G+7 -> tanh'd f32
            __half2 h4 = __floats2half2_rn(acc[i][0], acc[i][1]);
            *(unsigned int*)(outh + r * 256 + 8 * G + 4) =
                *reinterpret_cast<unsigned int*>(&h4);
            float2 tf = make_float2(tanhf_fast(acc[i][2]), tanhf_fast(acc[i][3]));
            *(float2*)(outf + r * 64 + 2 * G) = tf;
        }
    }
}

// ---------------------------------------------------------------------------
// Scores 6:2 hybrid: c%8 {0..5} on MUFU (h2), {6,7} on FMA pipe (f32
// addition formula, 1 Newton). CTA 32d x 64e, 256 thr.
// Thread (dg = t>>5, el = t&31): 4 d's x 2 e's (el, el+32).
// f pitch 66 words (conflict-free LDS.64); fills use uint2 (8B, alignment-safe).
// ---------------------------------------------------------------------------
#define EPH_O 0
#define EPF_O (64 * 132)
#define DPH_O (EPF_O + 64 * 66)
#define DPF_O (DPH_O + 32 * 132)
#define VH_O  (DPF_O + 32 * 66)
#define VFN_O (VH_O + 128)
#define SCORES_SMEM ((VFN_O + 64) * 4)

__global__ __launch_bounds__(256, 2) void scores_kernel(const float* __restrict__ v_g) {
    extern __shared__ unsigned int smu[];
    unsigned int* eph = smu + EPH_O;            // 64 x 132 (128 used: 256 halves)
    float*        epf = (float*)(smu + EPF_O);  // 64 x 66 (64 used)
    unsigned int* dph = smu + DPH_O;            // 32 x 132
    float*        dpf = (float*)(smu + DPF_O);  // 32 x 66
    unsigned int* vh  = smu + VH_O;             // 32 groups x 4 (3 used)
    float*        vfn = (float*)(smu + VFN_O);  // 64 f32 (-v for c%8 6,7)

    const int b  = blockIdx.z;
    const int d0 = blockIdx.y * 32;
    const int e0 = blockIdx.x * 64;
    const int t  = threadIdx.x;

    const __half* ehsrc = g_enc_h + ((size_t)b * E_ + e0) * 256;
    for (int i = t; i < 64 * 32; i += 256) {
        int r = i >> 5, q = i & 31;
        uint4 s = ((const uint4*)ehsrc)[r * 32 + q];
        *(uint4*)(eph + r * 132 + q * 4) = s;
    }
    const float* efsrc = g_enc_f + ((size_t)b * E_ + e0) * 64;
    for (int i = t; i < 64 * 32; i += 256) {
        int r = i >> 5, q = i & 31;
        uint2 s = ((const uint2*)efsrc)[r * 32 + q];
        *(uint2*)(epf + r * 66 + q * 2) = s;
    }
    const __half* dhsrc = g_dec_h + ((size_t)b * D_ + d0) * 256;
    for (int i = t; i < 32 * 32; i += 256) {
        int r = i >> 5, q = i & 31;
        uint4 s = ((const uint4*)dhsrc)[r * 32 + q];
        *(uint4*)(dph + r * 132 + q * 4) = s;
    }
    const float* dfsrc = g_dec_f + ((size_t)b * D_ + d0) * 64;
    for (int i = t; i < 32 * 32; i += 256) {
        int r = i >> 5, q = i & 31;
        uint2 s = ((const uint2*)dfsrc)[r * 32 + q];
        *(uint2*)(dpf + r * 66 + q * 2) = s;
    }
    if (t < 128) {
        int g = t >> 2, w = t & 3;
        unsigned int val = 0;
        if (w < 3) {
            __half2 p = __floats2half2_rn(v_g[8 * g + 2 * w], v_g[8 * g + 2 * w + 1]);
            val = *reinterpret_cast<unsigned int*>(&p);
        }
        vh[t] = val;
    }
    if (t < 64) {
        vfn[t] = -v_g[8 * (t >> 1) + 6 + (t & 1)];
    }
    __syncthreads();

    const int el = t & 31;
    const int dg = t >> 5;
    const unsigned int* eh0 = eph + el * 132;
    const unsigned int* eh1 = eph + (el + 32) * 132;
    const float* ef0 = epf + el * 66;
    const float* ef1 = epf + (el + 32) * 66;
    const unsigned int* dhb = dph + (dg * 4) * 132;
    const float* dfb = dpf + (dg * 4) * 66;

    __half2 ah[8];
    ull af[8];
    float facc[8];
#pragma unroll
    for (int p = 0; p < 8; p++) {
        ah[p] = __floats2half2_rn(0.f, 0.f);
        af[p] = 0ull;
        facc[p] = 0.f;
    }

    for (int g = 0; g < 32; g++) {
        uint4 vhp = *(const uint4*)(vh + 4 * g);
        __half2 v0 = u2h(vhp.x), v1 = u2h(vhp.y), v2 = u2h(vhp.z);
        ull nv = *(const ull*)(vfn + 2 * g);
        uint4 e0hq = *(const uint4*)(eh0 + 4 * g);
        uint4 e1hq = *(const uint4*)(eh1 + 4 * g);
        ull e0f = *(const ull*)(ef0 + 2 * g);
        ull e1f = *(const ull*)(ef1 + 2 * g);
#pragma unroll
        for (int i = 0; i < 4; i++) {
            uint4 dh = *(const uint4*)(dhb + i * 132 + 4 * g);
            ull df = *(const ull*)(dfb + i * 66 + 2 * g);
            __half2 dh0 = u2h(dh.x), dh1 = u2h(dh.y), dh2 = u2h(dh.z);
            __half2 s0 = ah[i * 2];
            s0 = __hfma2(tanh2h(__hadd2(dh0, u2h(e0hq.x))), v0, s0);
            s0 = __hfma2(tanh2h(__hadd2(dh1, u2h(e0hq.y))), v1, s0);
            s0 = __hfma2(tanh2h(__hadd2(dh2, u2h(e0hq.z))), v2, s0);
            ah[i * 2] = s0;
            __half2 s1 = ah[i * 2 + 1];
            s1 = __hfma2(tanh2h(__hadd2(dh0, u2h(e1hq.x))), v0, s1);
            s1 = __hfma2(tanh2h(__hadd2(dh1, u2h(e1hq.y))), v1, s1);
            s1 = __hfma2(tanh2h(__hadd2(dh2, u2h(e1hq.z))), v2, s1);
            ah[i * 2 + 1] = s1;
            af[i * 2]     = tanh_sum_acc1(df, e0f, nv, af[i * 2]);
            af[i * 2 + 1] = tanh_sum_acc1(df, e1f, nv, af[i * 2 + 1]);
        }
        if ((g & 3) == 3) {
#pragma unroll
            for (int p = 0; p < 8; p++) {
                float2 f = __half22float2(ah[p]);
                facc[p] += f.x + f.y;
                ah[p] = __floats2half2_rn(0.f, 0.f);
            }
        }
    }

#pragma unroll
    for (int p = 0; p < 8; p++) {
        float lo, hi;
        asm("mov.b64 {%0, %1}, %2;" : "=f"(lo), "=f"(hi) : "l"(af[p]));
        facc[p] += lo + hi;
    }

#pragma unroll
    for (int i = 0; i < 4; i++) {
        float* srow = g_scores + ((size_t)b * D_ + d0 + dg * 4 + i) * E_ + e0 + el;
        srow[0]  = facc[i * 2];
        srow[32] = facc[i * 2 + 1];
    }
}

// ---------------------------------------------------------------------------
// Masked log-softmax, one warp per row (E=512, 16 elems/lane).
// ---------------------------------------------------------------------------
__global__ __launch_bounds__(256) void softmax_kernel(const int* __restrict__ mask,
                                                      float* __restrict__ out) {
    const int row  = blockIdx.x * 8 + (threadIdx.x >> 5);
    const int lane = threadIdx.x & 31;

    const float4* s = (const float4*)(g_scores + (size_t)row * E_);
    const int4*   m = (const int4*)(mask + (size_t)row * E_);

    float x[16];
    float vmax = -3.0e38f;
#pragma unroll
    for (int q = 0; q < 4; q++) {
        float4 sv = s[q * 32 + lane];
        int4   mv = m[q * 32 + lane];
        x[4 * q + 0] = mv.x ? sv.x : NEG_INF;
        x[4 * q + 1] = mv.y ? sv.y : NEG_INF;
        x[4 * q + 2] = mv.z ? sv.z : NEG_INF;
        x[4 * q + 3] = mv.w ? sv.w : NEG_INF;
        vmax = fmaxf(vmax, fmaxf(fmaxf(x[4 * q], x[4 * q + 1]),
                                 fmaxf(x[4 * q + 2], x[4 * q + 3])));
    }
#pragma unroll
    for (int o = 16; o; o >>= 1)
        vmax = fmaxf(vmax, __shfl_xor_sync(0xffffffffu, vmax, o));

    float sum = 0.f;
#pragma unroll
    for (int k = 0; k < 16; k++) sum += __expf(x[k] - vmax);
#pragma unroll
    for (int o = 16; o; o >>= 1)
        sum += __shfl_xor_sync(0xffffffffu, sum, o);

    const float lse = vmax + logf(sum);

    float* orow = out + (size_t)row * E_;
#pragma unroll
    for (int q = 0; q < 4; q++) {
        float4 o4 = make_float4(x[4 * q] - lse, x[4 * q + 1] - lse,
                                x[4 * q + 2] - lse, x[4 * q + 3] - lse);
        ((float4*)orow)[q * 32 + lane] = o4;
    }
}

// ---------------------------------------------------------------------------
extern "C" void kernel_launch(void* const* d_in, const int* in_sizes, int n_in,
                              void* d_out, int out_size) {
    const float* decoder = (const float*)d_in[0];
    const float* encoder = (const float*)d_in[1];
    const int*   mask    = (const int*)d_in[2];
    const float* W1      = (const float*)d_in[3];
    const float* W2      = (const float*)d_in[4];
    const float* v       = (const float*)d_in[5];
    float* out           = (float*)d_out;

    cudaFuncSetAttribute(scores_kernel,
                         cudaFuncAttributeMaxDynamicSharedMemorySize, SCORES_SMEM);

    gemm_fused_kernel<<<dim3(8, 24, B_), 128>>>(encoder, decoder, W1, W2);
    scores_kernel<<<dim3(E_ / 64, D_ / 32, B_), 256, SCORES_SMEM>>>(v);
    softmax_kernel<<<B_ * D_ / 8, 256>>>(mask, out);
}

// round 12
// speedup vs baseline: 1.1508x; 1.1508x over previous
#include <cuda_runtime.h>
#include <cuda_fp16.h>
#include <cuda_bf16.h>
#include <cstddef>

#define B_   4
#define D_   256
#define E_   512
#define C_   256
#define NEG_INF -1e9f

typedef unsigned long long ull;

// Scratch. h buffers: proj as half for c%8 in {0..3}: row = 128 halves,
// position (c>>3)*4 + (c&3). f buffers: tanh(proj) as f32 for c%8 in {4..7}:
// row = 128 floats, position (c>>3)*4 + (c&3) - 4.
__device__ __half g_enc_h[B_ * E_ * 128];
__device__ float  g_enc_f[B_ * E_ * 128];
__device__ __half g_dec_h[B_ * D_ * 128];
__device__ float  g_dec_f[B_ * D_ * 128];
__device__ float  g_scores[B_ * D_ * E_];

__device__ __forceinline__ __half2 tanh2h(__half2 x) {
    unsigned int r, xi = *reinterpret_cast<unsigned int*>(&x);
    asm("tanh.approx.f16x2 %0, %1;" : "=r"(r) : "r"(xi));
    return *reinterpret_cast<__half2*>(&r);
}
__device__ __forceinline__ __half2 u2h(unsigned int u) {
    return *reinterpret_cast<__half2*>(&u);
}
__device__ __forceinline__ float tanhf_fast(float x) {
    float y; asm("tanh.approx.f32 %0, %1;" : "=f"(y) : "f"(x)); return y;
}
__device__ __forceinline__ ull fma2_(ull a, ull b, ull c) {
    ull d; asm("fma.rn.f32x2 %0, %1, %2, %3;" : "=l"(d) : "l"(a), "l"(b), "l"(c)); return d;
}
__device__ __forceinline__ ull add2_(ull a, ull b) {
    ull d; asm("add.rn.f32x2 %0, %1, %2;" : "=l"(d) : "l"(a), "l"(b)); return d;
}
__device__ __forceinline__ ull mul2_(ull a, ull b) {
    ull d; asm("mul.rn.f32x2 %0, %1, %2;" : "=l"(d) : "l"(a), "l"(b)); return d;
}

#define ONE2_  0x3F8000003F800000ull
#define NTWO2_ 0xC0000000C0000000ull

// tanh(a+b)*v via addition formula, 1 Newton step.
// ta, tb = packed f32 tanh pairs; nv = packed(-v). 6 f32x2 + 2 ALU.
__device__ __forceinline__ ull tanh_sum_acc1(ull ta, ull tb, ull nv, ull acc) {
    ull num = add2_(ta, tb);
    ull den = fma2_(ta, tb, ONE2_);          // 1 + ta*tb in (0,2]
    ull r0;
    asm("{\n\t.reg .b32 lo, hi;\n\t"
        "mov.b64 {lo, hi}, %1;\n\t"
        "sub.u32 lo, 0x7EF311C3, lo;\n\t"
        "sub.u32 hi, 0x7EF311C3, hi;\n\t"
        "mov.b64 %0, {lo, hi};\n\t}" : "=l"(r0) : "l"(den));
    ull u1  = fma2_(den, r0, NTWO2_);        // d*r0 - 2
    ull r1n = mul2_(r0, u1);                 // -r1 ~ -1/den
    ull t   = mul2_(num, r1n);               // -tanh(a+b)
    return fma2_(t, nv, acc);                // acc + tanh*v
}

__device__ __forceinline__ ull pku(unsigned lo, unsigned hi) {
    return ((ull)hi << 32) | lo;
}

// ---------------------------------------------------------------------------
// Fused GEMM (R10 geometry): tile 64x32, BK=16, 128 thr, 4x4 micro.
// Epilogue 4:4 split: tx even -> 4 halves (c%8 0..3) to h buffer;
// tx odd -> 4 tanh'd f32 (c%8 4..7) to f buffer.
// ---------------------------------------------------------------------------
__global__ __launch_bounds__(128) void gemm_fused_kernel(
        const float* __restrict__ enc, const float* __restrict__ dec,
        const float* __restrict__ W1,  const float* __restrict__ W2) {
    __shared__ float Xs[16][68];
    __shared__ float Ws[16][36];

    const int b  = blockIdx.z;
    const int yt = blockIdx.y;
    const bool is_enc = (yt < 8);
    const int R      = is_enc ? E_ : D_;
    const int row0   = (is_enc ? yt : yt - 8) * 64;
    const int col0   = blockIdx.x * 32;
    const float* X   = is_enc ? enc : dec;
    const float* W   = is_enc ? W1  : W2;
    __half* outh     = is_enc ? g_enc_h : g_dec_h;
    float*  outf     = is_enc ? g_enc_f : g_dec_f;

    const int t  = threadIdx.x;
    const int lr = t >> 2;
    const int lc = (t & 3) << 2;
    const int ty = t >> 3;
    const int tx = t & 7;

    const float* Xb = X + ((size_t)b * R + row0 + lr) * C_ + lc;
    const float* Wb = W + (size_t)(col0 + lr) * C_ + lc;

    float4 xa0 = *(const float4*)Xb;
    float4 xa1 = *(const float4*)(Xb + 32 * C_);
    float4 wa  = *(const float4*)Wb;

    float acc[4][4];
#pragma unroll
    for (int i = 0; i < 4; i++)
#pragma unroll
        for (int j = 0; j < 4; j++) acc[i][j] = 0.f;

    for (int k0 = 0; k0 < C_; k0 += 16) {
        Xs[lc + 0][lr] = xa0.x; Xs[lc + 1][lr] = xa0.y;
        Xs[lc + 2][lr] = xa0.z; Xs[lc + 3][lr] = xa0.w;
        Xs[lc + 0][lr + 32] = xa1.x; Xs[lc + 1][lr + 32] = xa1.y;
        Xs[lc + 2][lr + 32] = xa1.z; Xs[lc + 3][lr + 32] = xa1.w;
        Ws[lc + 0][lr] = wa.x; Ws[lc + 1][lr] = wa.y;
        Ws[lc + 2][lr] = wa.z; Ws[lc + 3][lr] = wa.w;
        __syncthreads();
        if (k0 + 16 < C_) {
            xa0 = *(const float4*)(Xb + k0 + 16);
            xa1 = *(const float4*)(Xb + 32 * C_ + k0 + 16);
            wa  = *(const float4*)(Wb + k0 + 16);
        }
#pragma unroll
        for (int kk = 0; kk < 16; kk++) {
            float4 a4 = *(const float4*)&Xs[kk][ty * 4];
            float4 b4 = *(const float4*)&Ws[kk][tx * 4];
            float a[4] = {a4.x, a4.y, a4.z, a4.w};
            float bb[4] = {b4.x, b4.y, b4.z, b4.w};
#pragma unroll
            for (int i = 0; i < 4; i++)
#pragma unroll
                for (int j = 0; j < 4; j++)
                    acc[i][j] = fmaf(a[i], bb[j], acc[i][j]);
        }
        __syncthreads();
    }

    const int G = (col0 >> 3) + (tx >> 1);   // global c-group of this thread
#pragma unroll
    for (int i = 0; i < 4; i++) {
        const size_t r = (size_t)b * R + row0 + ty * 4 + i;
        if ((tx & 1) == 0) {
            // cols 8G..8G+3 -> h buffer (positions 4G..4G+3)
            __half2 h0 = __floats2half2_rn(acc[i][0], acc[i][1]);
            __half2 h1 = __floats2half2_rn(acc[i][2], acc[i][3]);
            uint2 pk = make_uint2(*reinterpret_cast<unsigned int*>(&h0),
                                  *reinterpret_cast<unsigned int*>(&h1));
            *(uint2*)(outh + r * 128 + 4 * G) = pk;
        } else {
            // cols 8G+4..8G+7 -> tanh'd f32 (positions 4G..4G+3)
            float4 tq = make_float4(tanhf_fast(acc[i][0]), tanhf_fast(acc[i][1]),
                                    tanhf_fast(acc[i][2]), tanhf_fast(acc[i][3]));
            *(float4*)(outf + r * 128 + 4 * G) = tq;
        }
    }
}

// ---------------------------------------------------------------------------
// Scores, warp-specialized 4+4: CTA 32d x 64e, 256 thr.
// Warps 0-3 (MUFU-only): c%8 {0..3} via tanh.f16x2; warp w covers d rows
//   8w..8w+7, lane el covers e = el, el+32 -> 16 h2 accs.
// Warps 4-7 (FMA-only): c%8 {4..7} via f32x2 addition formula; same (d,e)
//   mapping with w-4 -> 16 ull accs.
// Partials combined via smem ps[], FMA warps write final scores.
// ---------------------------------------------------------------------------
#define EPH_O 0
#define DPH_O (EPH_O + 64 * 66)
#define EPF_O (DPH_O + 32 * 66)
#define DPF_O (EPF_O + 64 * 132)
#define VH_O  (DPF_O + 32 * 132)
#define VFN_O (VH_O + 64)
#define PS_O  (VFN_O + 128)
#define SCORES_SMEM ((PS_O + 2048) * 4)

__global__ __launch_bounds__(256, 2) void scores_kernel(const float* __restrict__ v_g) {
    extern __shared__ unsigned int smu[];
    unsigned int* eph = smu + EPH_O;            // 64 rows x 66 (64 h2 words used)
    unsigned int* dph = smu + DPH_O;            // 32 x 66
    float*        epf = (float*)(smu + EPF_O);  // 64 x 132 (128 f32 used)
    float*        dpf = (float*)(smu + DPF_O);  // 32 x 132
    unsigned int* vh  = smu + VH_O;             // 64 h2 words (c%8 0..3)
    float*        vfn = (float*)(smu + VFN_O);  // 128 f32 (-v, c%8 4..7)
    float*        ps  = (float*)(smu + PS_O);   // 32d x 64e MUFU partials

    const int b  = blockIdx.z;
    const int d0 = blockIdx.y * 32;
    const int e0 = blockIdx.x * 64;
    const int t  = threadIdx.x;

    // eph fills: rows of 128 halves = 32 uint2; pitch 66 (uint2-aligned).
    const __half* ehsrc = g_enc_h + ((size_t)b * E_ + e0) * 128;
    for (int i = t; i < 64 * 32; i += 256) {
        int r = i >> 5, q = i & 31;
        uint2 s = ((const uint2*)ehsrc)[r * 32 + q];
        *(uint2*)(eph + r * 66 + q * 2) = s;
    }
    const __half* dhsrc = g_dec_h + ((size_t)b * D_ + d0) * 128;
    for (int i = t; i < 32 * 32; i += 256) {
        int r = i >> 5, q = i & 31;
        uint2 s = ((const uint2*)dhsrc)[r * 32 + q];
        *(uint2*)(dph + r * 66 + q * 2) = s;
    }
    // f fills: rows of 128 f32 = 32 uint4; pitch 132 (uint4-aligned).
    const float* efsrc = g_enc_f + ((size_t)b * E_ + e0) * 128;
    for (int i = t; i < 64 * 32; i += 256) {
        int r = i >> 5, q = i & 31;
        uint4 s = ((const uint4*)efsrc)[r * 32 + q];
        *(uint4*)(epf + r * 132 + q * 4) = s;
    }
    const float* dfsrc = g_dec_f + ((size_t)b * D_ + d0) * 128;
    for (int i = t; i < 32 * 32; i += 256) {
        int r = i >> 5, q = i & 31;
        uint4 s = ((const uint4*)dfsrc)[r * 32 + q];
        *(uint4*)(dpf + r * 132 + q * 4) = s;
    }
    if (t < 64) {
        int g = t >> 1, h = t & 1;
        __half2 p = __floats2half2_rn(v_g[8 * g + 2 * h], v_g[8 * g + 2 * h + 1]);
        vh[t] = *reinterpret_cast<unsigned int*>(&p);
    }
    if (t < 128) {
        vfn[t] = -v_g[8 * (t >> 2) + 4 + (t & 3)];
    }
    __syncthreads();

    const int w  = t >> 5;
    const int el = t & 31;

    if (w < 4) {
        // ---------------- MUFU warps: c%8 in {0..3} ----------------
        const unsigned int* eh0 = eph + el * 66;
        const unsigned int* eh1 = eph + (el + 32) * 66;
        const unsigned int* dhb = dph + (8 * w) * 66;

        __half2 ah[16];
        float facc[16];
#pragma unroll
        for (int p = 0; p < 16; p++) {
            ah[p] = __floats2half2_rn(0.f, 0.f);
            facc[p] = 0.f;
        }

        for (int g = 0; g < 32; g++) {
            uint2 vv = *(const uint2*)(vh + 2 * g);
            __half2 v0 = u2h(vv.x), v1 = u2h(vv.y);
            uint2 ea = *(const uint2*)(eh0 + 2 * g);
            uint2 eb = *(const uint2*)(eh1 + 2 * g);
            __half2 ea0 = u2h(ea.x), ea1 = u2h(ea.y);
            __half2 eb0 = u2h(eb.x), eb1 = u2h(eb.y);
#pragma unroll
            for (int i = 0; i < 8; i++) {
                uint2 dhp = *(const uint2*)(dhb + i * 66 + 2 * g);
                __half2 dh0 = u2h(dhp.x), dh1 = u2h(dhp.y);
                __half2 s0 = ah[i * 2];
                s0 = __hfma2(tanh2h(__hadd2(dh0, ea0)), v0, s0);
                s0 = __hfma2(tanh2h(__hadd2(dh1, ea1)), v1, s0);
                ah[i * 2] = s0;
                __half2 s1 = ah[i * 2 + 1];
                s1 = __hfma2(tanh2h(__hadd2(dh0, eb0)), v0, s1);
                s1 = __hfma2(tanh2h(__hadd2(dh1, eb1)), v1, s1);
                ah[i * 2 + 1] = s1;
            }
            if ((g & 3) == 3) {
#pragma unroll
                for (int p = 0; p < 16; p++) {
                    float2 f = __half22float2(ah[p]);
                    facc[p] += f.x + f.y;
                    ah[p] = __floats2half2_rn(0.f, 0.f);
                }
            }
        }
        // write partials to ps[d][e]
#pragma unroll
        for (int i = 0; i < 8; i++) {
            ps[(8 * w + i) * 64 + el]      = facc[i * 2];
            ps[(8 * w + i) * 64 + el + 32] = facc[i * 2 + 1];
        }
    } else {
        // ---------------- FMA warps: c%8 in {4..7} ----------------
        const int w4 = w - 4;
        const float* ef0 = epf + el * 132;
        const float* ef1 = epf + (el + 32) * 132;
        const float* dfb = dpf + (8 * w4) * 132;

        ull af[16];
#pragma unroll
        for (int p = 0; p < 16; p++) af[p] = 0ull;

        for (int g = 0; g < 32; g++) {
            uint4 nvq = *(const uint4*)(vfn + 4 * g);
            ull nv0 = pku(nvq.x, nvq.y);
            ull nv1 = pku(nvq.z, nvq.w);
            uint4 e0q = *(const uint4*)(ef0 + 4 * g);
            uint4 e1q = *(const uint4*)(ef1 + 4 * g);
            ull e0a = pku(e0q.x, e0q.y), e0b = pku(e0q.z, e0q.w);
            ull e1a = pku(e1q.x, e1q.y), e1b = pku(e1q.z, e1q.w);
#pragma unroll
            for (int i = 0; i < 8; i++) {
                uint4 dq = *(const uint4*)(dfb + i * 132 + 4 * g);
                ull da = pku(dq.x, dq.y), db = pku(dq.z, dq.w);
                ull a0 = af[i * 2];
                a0 = tanh_sum_acc1(da, e0a, nv0, a0);
                a0 = tanh_sum_acc1(db, e0b, nv1, a0);
                af[i * 2] = a0;
                ull a1 = af[i * 2 + 1];
                a1 = tanh_sum_acc1(da, e1a, nv0, a1);
                a1 = tanh_sum_acc1(db, e1b, nv1, a1);
                af[i * 2 + 1] = a1;
            }
        }
        // keep af in registers; combined after sync
        __syncthreads();
#pragma unroll
        for (int i = 0; i < 8; i++) {
            float lo0, hi0, lo1, hi1;
            asm("mov.b64 {%0, %1}, %2;" : "=f"(lo0), "=f"(hi0) : "l"(af[i * 2]));
            asm("mov.b64 {%0, %1}, %2;" : "=f"(lo1), "=f"(hi1) : "l"(af[i * 2 + 1]));
            float m0 = ps[(8 * w4 + i) * 64 + el];
            float m1 = ps[(8 * w4 + i) * 64 + el + 32];
            float* srow = g_scores + ((size_t)b * D_ + d0 + 8 * w4 + i) * E_ + e0 + el;
            srow[0]  = m0 + lo0 + hi0;
            srow[32] = m1 + lo1 + hi1;
        }
        return;
    }
    __syncthreads();   // MUFU warps arrive here (matches FMA warps' sync)
}

// ---------------------------------------------------------------------------
// Masked log-softmax, one warp per row (E=512, 16 elems/lane).
// ---------------------------------------------------------------------------
__global__ __launch_bounds__(256) void softmax_kernel(const int* __restrict__ mask,
                                                      float* __restrict__ out) {
    const int row  = blockIdx.x * 8 + (threadIdx.x >> 5);
    const int lane = threadIdx.x & 31;

    const float4* s = (const float4*)(g_scores + (size_t)row * E_);
    const int4*   m = (const int4*)(mask + (size_t)row * E_);

    float x[16];
    float vmax = -3.0e38f;
#pragma unroll
    for (int q = 0; q < 4; q++) {
        float4 sv = s[q * 32 + lane];
        int4   mv = m[q * 32 + lane];
        x[4 * q + 0] = mv.x ? sv.x : NEG_INF;
        x[4 * q + 1] = mv.y ? sv.y : NEG_INF;
        x[4 * q + 2] = mv.z ? sv.z : NEG_INF;
        x[4 * q + 3] = mv.w ? sv.w : NEG_INF;
        vmax = fmaxf(vmax, fmaxf(fmaxf(x[4 * q], x[4 * q + 1]),
                                 fmaxf(x[4 * q + 2], x[4 * q + 3])));
    }
#pragma unroll
    for (int o = 16; o; o >>= 1)
        vmax = fmaxf(vmax, __shfl_xor_sync(0xffffffffu, vmax, o));

    float sum = 0.f;
#pragma unroll
    for (int k = 0; k < 16; k++) sum += __expf(x[k] - vmax);
#pragma unroll
    for (int o = 16; o; o >>= 1)
        sum += __shfl_xor_sync(0xffffffffu, sum, o);

    const float lse = vmax + logf(sum);

    float* orow = out + (size_t)row * E_;
#pragma unroll
    for (int q = 0; q < 4; q++) {
        float4 o4 = make_float4(x[4 * q] - lse, x[4 * q + 1] - lse,
                                x[4 * q + 2] - lse, x[4 * q + 3] - lse);
        ((float4*)orow)[q * 32 + lane] = o4;
    }
}

// ---------------------------------------------------------------------------
extern "C" void kernel_launch(void* const* d_in, const int* in_sizes, int n_in,
                              void* d_out, int out_size) {
    const float* decoder = (const float*)d_in[0];
    const float* encoder = (const float*)d_in[1];
    const int*   mask    = (const int*)d_in[2];
    const float* W1      = (const float*)d_in[3];
    const float* W2      = (const float*)d_in[4];
    const float* v       = (const float*)d_in[5];
    float* out           = (float*)d_out;

    cudaFuncSetAttribute(scores_kernel,
                         cudaFuncAttributeMaxDynamicSharedMemorySize, SCORES_SMEM);

    gemm_fused_kernel<<<dim3(8, 12, B_), 128>>>(encoder, decoder, W1, W2);
    scores_kernel<<<dim3(E_ / 64, D_ / 32, B_), 256, SCORES_SMEM>>>(v);
    softmax_kernel<<<B_ * D_ / 8, 256>>>(mask, out);
}